// round 13
// baseline (speedup 1.0000x reference)
#include <cuda_runtime.h>
#include <cstdint>

#define Bn      8
#define Nn      8192
#define NPOINT  1024
#define NSAMPLE 32
#define PPT     8          // points per thread in FPS (Nn / 1024)

typedef unsigned long long ull;

// per-point feature table (B*N points x 128 ch)
__device__ float4 g_feat4[Bn * Nn * 32];          // 33.5 MB, row = point, 32 x float4

// ---------------------------------------------------------------------------
// packed f32x2 helpers — each half rounds exactly like the scalar .rn op
// ---------------------------------------------------------------------------
__device__ __forceinline__ ull pack2(float lo, float hi) {
    ull r; asm("mov.b64 %0, {%1,%2};" : "=l"(r) : "f"(lo), "f"(hi)); return r;
}
__device__ __forceinline__ void unpack2(ull v, float& lo, float& hi) {
    asm("mov.b64 {%0,%1}, %2;" : "=f"(lo), "=f"(hi) : "l"(v));
}
__device__ __forceinline__ ull add2(ull a, ull b) {
    ull r; asm("add.rn.f32x2 %0,%1,%2;" : "=l"(r) : "l"(a), "l"(b)); return r;
}
__device__ __forceinline__ ull mul2(ull a, ull b) {
    ull r; asm("mul.rn.f32x2 %0,%1,%2;" : "=l"(r) : "l"(a), "l"(b)); return r;
}
__device__ __forceinline__ ull fma2(ull a, ull b, ull c) {
    ull r; asm("fma.rn.f32x2 %0,%1,%2,%3;" : "=l"(r) : "l"(a), "l"(b), "l"(c)); return r;
}

// ---------------------------------------------------------------------------
// Shared-memory layouts for the fused kernel's two block roles
// ---------------------------------------------------------------------------
struct FpsSmem {                 // blocks 0..7 (FPS)
    float4 c4[Nn];               // 128 KB staged coords
    int    sel[NPOINT];
    ull    red[32];
    float4 q;
};

#define SW1_OFF  0               // float4[64]               -> 256 floats
#define SW2T_OFF 256             // float [64*64]  [c][o]    -> 4096 floats
#define SB2_OFF  (256 + 4096)               // float[64]
#define SW3_OFF  (256 + 4096 + 64)          // float[128*64] [o][c]
#define SB3_OFF  (256 + 4096 + 64 + 8192)   // float[128]
#define SMEM_FLOATS (256 + 4096 + 64 + 8192 + 128)

#define FUSED_SMEM ((int)(sizeof(FpsSmem) > SMEM_FLOATS * 4 ? sizeof(FpsSmem) : SMEM_FLOATS * 4))

// ---------------------------------------------------------------------------
// FUSED kernel: grid = 8 + 64 blocks, 1024 threads, 1 block/SM.
//   blocks 0..7   : FPS — reducer = warp 31 (highest issue priority),
//                   named-barrier arrive/sync split (one blocking wait per
//                   warp per iteration; reducer warp never blocks on bar#2).
//   blocks 8..71  : per-point feature MLP (1024 points/block), concurrent.
// ---------------------------------------------------------------------------
__global__ __launch_bounds__(1024, 1)
void fps_feat_kernel(const float* __restrict__ xyz, float* __restrict__ newxyz,
                     const float* __restrict__ w1, const float* __restrict__ b1,
                     const float* __restrict__ g1, const float* __restrict__ be1,
                     const float* __restrict__ m1, const float* __restrict__ v1,
                     const float* __restrict__ w2, const float* __restrict__ b2,
                     const float* __restrict__ g2, const float* __restrict__ be2,
                     const float* __restrict__ m2, const float* __restrict__ v2,
                     const float* __restrict__ w3, const float* __restrict__ b3,
                     const float* __restrict__ g3, const float* __restrict__ be3,
                     const float* __restrict__ m3, const float* __restrict__ v3,
                     float4* __restrict__ ft)
{
    extern __shared__ char raw[];
    const int t = threadIdx.x;

    if (blockIdx.x < Bn) {
        // =================== FPS role ========================================
        FpsSmem* sm = (FpsSmem*)raw;
        const int b = blockIdx.x;
        const int lane = t & 31, wid = t >> 5;
        const float* p = xyz + (size_t)b * Nn * 3;

        ull px2[4], py2[4], pz2[4];
        int mdi[PPT];
#pragma unroll
        for (int k = 0; k < 4; k++) {
            int i0 = t + (2 * k) * 1024;
            int i1 = i0 + 1024;
            px2[k] = pack2(p[3 * i0 + 0], p[3 * i1 + 0]);
            py2[k] = pack2(p[3 * i0 + 1], p[3 * i1 + 1]);
            pz2[k] = pack2(p[3 * i0 + 2], p[3 * i1 + 2]);
        }
#pragma unroll
        for (int j = 0; j < PPT; j++) mdi[j] = 0x7f800000;   // +inf bits

        for (int i = t; i < Nn; i += 1024)
            sm->c4[i] = make_float4(p[3 * i + 0], p[3 * i + 1], p[3 * i + 2], 0.f);
        if (t == 0) sm->sel[0] = 0;
        __syncthreads();

        float4 q = sm->c4[0];

        for (int it = 1; it < NPOINT; it++) {
            ull nqx2 = pack2(-q.x, -q.x);
            ull nqy2 = pack2(-q.y, -q.y);
            ull nqz2 = pack2(-q.z, -q.z);

#pragma unroll
            for (int k = 0; k < 4; k++) {
                ull dx = add2(px2[k], nqx2);
                ull dy = add2(py2[k], nqy2);
                ull dz = add2(pz2[k], nqz2);
                ull s  = add2(add2(mul2(dx, dx), mul2(dy, dy)), mul2(dz, dz));
                float d0, d1; unpack2(s, d0, d1);
                mdi[2 * k]     = min(mdi[2 * k],     __float_as_int(d0));
                mdi[2 * k + 1] = min(mdi[2 * k + 1], __float_as_int(d1));
            }

            int m0 = max(mdi[0], mdi[1]);
            int m1 = max(mdi[2], mdi[3]);
            int m2 = max(mdi[4], mdi[5]);
            int m3 = max(mdi[6], mdi[7]);
            int m  = max(max(m0, m1), max(m2, m3));

            int wm = __reduce_max_sync(0xffffffffu, m);
            int cand = 0x7fffffff;
            if (m == wm) {
#pragma unroll
                for (int j = 0; j < PPT; j++)
                    if (mdi[j] == wm) cand = min(cand, t + j * 1024);
            }
            int widx = __reduce_min_sync(0xffffffffu, cand);
            if (lane == 0)
                sm->red[wid] = ((ull)(unsigned)wm << 32) | (unsigned)widx;

            if (wid == 31) {
                // reducer: wait for all partials, reduce, publish, arrive-only
                asm volatile("bar.sync 1, 1024;" ::: "memory");
                ull pk = sm->red[lane];
                int v  = (int)(pk >> 32);
                int ix = (int)(unsigned)pk;
                int gm = __reduce_max_sync(0xffffffffu, v);
                int c2 = (v == gm) ? ix : 0x7fffffff;
                int win = __reduce_min_sync(0xffffffffu, c2);
                float4 qq = sm->c4[win];
                if (lane == 0) { sm->sel[it] = win; sm->q = qq; }
                asm volatile("bar.arrive 2, 1024;" ::: "memory");
                q = qq;                              // no blocking wait needed
            } else {
                // producer: non-blocking arrive on #1, single wait on #2
                asm volatile("bar.arrive 1, 1024;" ::: "memory");
                asm volatile("bar.sync 2, 1024;"   ::: "memory");
                q = sm->q;
            }
        }

        __syncthreads();   // order reducer's sel writes before epilogue reads

        // write new_xyz (B, NPOINT, 3)
        {
            int sel = sm->sel[t];
            float4 c = sm->c4[sel];
            float* o = newxyz + ((size_t)b * NPOINT + t) * 3;
            o[0] = c.x; o[1] = c.y; o[2] = c.z;
        }
    } else {
        // =================== feat role: per-point MLP ========================
        float*  smem = (float*)raw;
        float4* sw1  = (float4*)(smem + SW1_OFF);
        float*  sw2t = smem + SW2T_OFF;
        float*  sb2  = smem + SB2_OFF;
        float*  sw3  = smem + SW3_OFF;
        float*  sb3  = smem + SB3_OFF;

        for (int o = t; o < 64; o += 1024) {
            float s1 = g1[o] / sqrtf(v1[o] + 1e-5f);
            sw1[o] = make_float4(w1[o * 3 + 0] * s1, w1[o * 3 + 1] * s1,
                                 w1[o * 3 + 2] * s1, (b1[o] - m1[o]) * s1 + be1[o]);
            float s2 = g2[o] / sqrtf(v2[o] + 1e-5f);
            sb2[o] = (b2[o] - m2[o]) * s2 + be2[o];
        }
        for (int i = t; i < 64 * 64; i += 1024) {
            int o = i >> 6, c = i & 63;
            float s2 = g2[o] / sqrtf(v2[o] + 1e-5f);
            sw2t[c * 64 + o] = w2[o * 64 + c] * s2;   // transposed [c][o]
        }
        for (int i = t; i < 128 * 64; i += 1024) {
            int o = i >> 6;
            float s3 = g3[o] / sqrtf(v3[o] + 1e-5f);
            sw3[i] = w3[i] * s3;
        }
        for (int o = t; o < 128; o += 1024) {
            float s3 = g3[o] / sqrtf(v3[o] + 1e-5f);
            sb3[o] = (b3[o] - m3[o]) * s3 + be3[o];
        }
        __syncthreads();

        const int pt = (blockIdx.x - Bn) * 1024 + t;   // global point id 0..65535
        const float x = __ldg(xyz + 3 * pt + 0);
        const float y = __ldg(xyz + 3 * pt + 1);
        const float z = __ldg(xyz + 3 * pt + 2);

        ull h2p[32];
        {
            const ull* sb2p = (const ull*)sb2;
#pragma unroll
            for (int k = 0; k < 32; k++) h2p[k] = sb2p[k];
        }

        for (int c = 0; c < 64; c++) {
            float4 wc = sw1[c];
            float h1 = fmaxf(fmaf(x, wc.x, fmaf(y, wc.y, fmaf(z, wc.z, wc.w))), 0.f);
            ull h1p = pack2(h1, h1);
            const ulonglong2* row = (const ulonglong2*)(sw2t + c * 64);
#pragma unroll
            for (int k = 0; k < 16; k++) {
                ulonglong2 w = row[k];
                h2p[2 * k]     = fma2(w.x, h1p, h2p[2 * k]);
                h2p[2 * k + 1] = fma2(w.y, h1p, h2p[2 * k + 1]);
            }
        }
#pragma unroll
        for (int k = 0; k < 32; k++) {
            float a, c2; unpack2(h2p[k], a, c2);
            h2p[k] = pack2(fmaxf(a, 0.f), fmaxf(c2, 0.f));
        }

        float4* outr = ft + (size_t)pt * 32;
        for (int o4 = 0; o4 < 32; o4++) {
            float vv[4];
#pragma unroll
            for (int j = 0; j < 4; j++) {
                int o = o4 * 4 + j;
                const ulonglong2* row = (const ulonglong2*)(sw3 + o * 64);
                ull a0 = 0ull, a1 = 0ull;
#pragma unroll
                for (int k = 0; k < 16; k++) {
                    ulonglong2 w = row[k];
                    a0 = fma2(w.x, h2p[2 * k],     a0);
                    a1 = fma2(w.y, h2p[2 * k + 1], a1);
                }
                float s0, s1, s2, s3; unpack2(a0, s0, s1); unpack2(a1, s2, s3);
                vv[j] = fmaxf((s0 + s1) + (s2 + s3) + sb3[o], 0.f);
            }
            outr[o4] = make_float4(vv[0], vv[1], vv[2], vv[3]);
        }
    }
}

// ---------------------------------------------------------------------------
// FUSED ball query + gather-max pooling: one WARP per center.
//   phase 1: ballot + prefix-popcount ordered radius scan (exact reference
//            arithmetic, per-center early exit) — indices land in shared.
//   phase 2: lane owns 4 channels; loop over the 32 sampled points reading
//            coalesced 512B rows of the feature table (L2-resident).
// No gmem ball table, one fewer launch.
// ---------------------------------------------------------------------------
__global__ __launch_bounds__(256)
void bqpool_kernel(const float* __restrict__ xyz, const float* __restrict__ newxyz,
                   const float4* __restrict__ ft, float* __restrict__ feat)
{
    __shared__ int idxbuf[8][NSAMPLE];

    const int w = threadIdx.x >> 5;                        // warp in block
    const int lane = threadIdx.x & 31;
    const int c = blockIdx.x * 8 + w;                      // center id 0..8191
    const int b = c >> 10;
    const int s = c & 1023;
    const float* p = xyz + (size_t)b * Nn * 3;

    const float qx = __ldg(newxyz + 3 * c + 0);
    const float qy = __ldg(newxyz + 3 * c + 1);
    const float qz = __ldg(newxyz + 3 * c + 2);

    int cnt = 0;
    for (int base = 0; base < Nn; base += 32) {
        const int i = base + lane;
        float dx = __fadd_rn(__ldg(p + 3 * i + 0), -qx);
        float dy = __fadd_rn(__ldg(p + 3 * i + 1), -qy);
        float dz = __fadd_rn(__ldg(p + 3 * i + 2), -qz);
        float d  = __fadd_rn(__fadd_rn(__fmul_rn(dx, dx), __fmul_rn(dy, dy)),
                             __fmul_rn(dz, dz));
        const bool valid = d < 0.04f;
        const unsigned mask = __ballot_sync(0xffffffffu, valid);
        if (valid) {
            int pos = cnt + __popc(mask & ((1u << lane) - 1u));
            if (pos < NSAMPLE) idxbuf[w][pos] = i;
        }
        cnt += __popc(mask);
        if (cnt >= NSAMPLE) break;
    }
    if (cnt < NSAMPLE) {                       // reference pads with 0
        int sl = cnt + lane;
        if (sl < NSAMPLE) idxbuf[w][sl] = 0;
    }
    __syncwarp();

    // gather-max pool over the 32 samples
    const float4* base4 = ft + ((size_t)b * Nn) * 32;
    float4 mx = make_float4(0.f, 0.f, 0.f, 0.f);   // post-ReLU values are >= 0
#pragma unroll 4
    for (int smp = 0; smp < NSAMPLE; smp++) {
        int is = idxbuf[w][smp];                   // broadcast LDS
        float4 v = __ldg(base4 + (size_t)is * 32 + lane);
        mx.x = fmaxf(mx.x, v.x);
        mx.y = fmaxf(mx.y, v.y);
        mx.z = fmaxf(mx.z, v.z);
        mx.w = fmaxf(mx.w, v.w);
    }

    float* o = feat + ((size_t)b * 128 + lane * 4) * NPOINT + s;
    o[0 * NPOINT] = mx.x;
    o[1 * NPOINT] = mx.y;
    o[2 * NPOINT] = mx.z;
    o[3 * NPOINT] = mx.w;
}

// ---------------------------------------------------------------------------
extern "C" void kernel_launch(void* const* d_in, const int* in_sizes, int n_in,
                              void* d_out, int out_size)
{
    const float* xyz = (const float*)d_in[0];
    const float* w1  = (const float*)d_in[1];
    const float* b1  = (const float*)d_in[2];
    const float* g1  = (const float*)d_in[3];
    const float* be1 = (const float*)d_in[4];
    const float* m1  = (const float*)d_in[5];
    const float* v1  = (const float*)d_in[6];
    const float* w2  = (const float*)d_in[7];
    const float* b2  = (const float*)d_in[8];
    const float* g2  = (const float*)d_in[9];
    const float* be2 = (const float*)d_in[10];
    const float* m2  = (const float*)d_in[11];
    const float* v2  = (const float*)d_in[12];
    const float* w3  = (const float*)d_in[13];
    const float* b3  = (const float*)d_in[14];
    const float* g3  = (const float*)d_in[15];
    const float* be3 = (const float*)d_in[16];
    const float* m3  = (const float*)d_in[17];
    const float* v3  = (const float*)d_in[18];

    float* out    = (float*)d_out;
    float* newxyz = out;                             // (B, NPOINT, 3)
    float* feat   = out + (size_t)Bn * NPOINT * 3;   // (B, 128, NPOINT)

    float4* ft = nullptr;
    cudaGetSymbolAddress((void**)&ft, g_feat4);

    cudaFuncSetAttribute(fps_feat_kernel,
                         cudaFuncAttributeMaxDynamicSharedMemorySize, FUSED_SMEM);

    // blocks 0..7: FPS (8 SMs); blocks 8..71: per-point MLP concurrently.
    fps_feat_kernel<<<Bn + (Bn * Nn) / 1024, 1024, FUSED_SMEM>>>(
        xyz, newxyz,
        w1, b1, g1, be1, m1, v1,
        w2, b2, g2, be2, m2, v2,
        w3, b3, g3, be3, m3, v3,
        ft);
    bqpool_kernel<<<(Bn * NPOINT) / 8, 256>>>(xyz, newxyz, ft, feat);
}

// round 14
// speedup vs baseline: 1.1046x; 1.1046x over previous
#include <cuda_runtime.h>
#include <cstdint>

#define Bn      8
#define Nn      8192
#define NPOINT  1024
#define NSAMPLE 32
#define PPT     8          // points per thread in FPS (Nn / 1024)

#define FEAT_BLOCKS 32
#define FEAT_PTS    ((Bn * Nn) / FEAT_BLOCKS)   // 2048 points per feat block

typedef unsigned long long ull;

// scratch: ball query indices + per-point feature table (B*N points x 128 ch)
__device__ int    g_ball_idx[Bn * NPOINT * NSAMPLE];
__device__ float4 g_feat4[Bn * Nn * 32];          // 33.5 MB, row = point, 32 x float4

// ---------------------------------------------------------------------------
// packed f32x2 helpers — each half rounds exactly like the scalar .rn op
// ---------------------------------------------------------------------------
__device__ __forceinline__ ull pack2(float lo, float hi) {
    ull r; asm("mov.b64 %0, {%1,%2};" : "=l"(r) : "f"(lo), "f"(hi)); return r;
}
__device__ __forceinline__ void unpack2(ull v, float& lo, float& hi) {
    asm("mov.b64 {%0,%1}, %2;" : "=f"(lo), "=f"(hi) : "l"(v));
}
__device__ __forceinline__ ull add2(ull a, ull b) {
    ull r; asm("add.rn.f32x2 %0,%1,%2;" : "=l"(r) : "l"(a), "l"(b)); return r;
}
__device__ __forceinline__ ull mul2(ull a, ull b) {
    ull r; asm("mul.rn.f32x2 %0,%1,%2;" : "=l"(r) : "l"(a), "l"(b)); return r;
}
__device__ __forceinline__ ull fma2(ull a, ull b, ull c) {
    ull r; asm("fma.rn.f32x2 %0,%1,%2,%3;" : "=l"(r) : "l"(a), "l"(b), "l"(c)); return r;
}

// ---------------------------------------------------------------------------
// Shared-memory layouts for the fused kernel's two block roles
// ---------------------------------------------------------------------------
struct FpsSmem {                 // blocks 0..7 (FPS)
    float4 c4[Nn];               // 128 KB staged coords
    int    sel[NPOINT];
    ull    red[32];
    float4 q;
};

#define SW1_OFF  0               // float4[64]               -> 256 floats
#define SW2T_OFF 256             // float [64*64]  [c][o]    -> 4096 floats
#define SB2_OFF  (256 + 4096)               // float[64]
#define SW3_OFF  (256 + 4096 + 64)          // float[128*64] [o][c]
#define SB3_OFF  (256 + 4096 + 64 + 8192)   // float[128]
#define SMEM_FLOATS (256 + 4096 + 64 + 8192 + 128)

#define FUSED_SMEM ((int)(sizeof(FpsSmem) > SMEM_FLOATS * 4 ? sizeof(FpsSmem) : SMEM_FLOATS * 4))

// ---------------------------------------------------------------------------
// FUSED kernel: grid = 8 + 32 blocks, 1024 threads, 1 block/SM.
//   blocks 0..7   : FPS (R7/R11-proven two-barrier structure) — 8 SMs
//   blocks 8..39  : per-point feature MLP, 2048 points/block (2 per thread).
//                   Fewer concurrent FMA SMs -> less DVFS/power interference
//                   with the latency-bound FPS blocks; still finishes well
//                   inside the FPS window.
// ---------------------------------------------------------------------------
__global__ __launch_bounds__(1024, 1)
void fps_feat_kernel(const float* __restrict__ xyz, float* __restrict__ newxyz,
                     const float* __restrict__ w1, const float* __restrict__ b1,
                     const float* __restrict__ g1, const float* __restrict__ be1,
                     const float* __restrict__ m1, const float* __restrict__ v1,
                     const float* __restrict__ w2, const float* __restrict__ b2,
                     const float* __restrict__ g2, const float* __restrict__ be2,
                     const float* __restrict__ m2, const float* __restrict__ v2,
                     const float* __restrict__ w3, const float* __restrict__ b3,
                     const float* __restrict__ g3, const float* __restrict__ be3,
                     const float* __restrict__ m3, const float* __restrict__ v3,
                     float4* __restrict__ ft)
{
    extern __shared__ char raw[];
    const int t = threadIdx.x;

    if (blockIdx.x < Bn) {
        // =================== FPS role (R11 structure, verbatim) =============
        FpsSmem* sm = (FpsSmem*)raw;
        const int b = blockIdx.x;
        const int lane = t & 31, wid = t >> 5;
        const float* p = xyz + (size_t)b * Nn * 3;

        ull px2[4], py2[4], pz2[4];
        int mdi[PPT];
#pragma unroll
        for (int k = 0; k < 4; k++) {
            int i0 = t + (2 * k) * 1024;
            int i1 = i0 + 1024;
            px2[k] = pack2(p[3 * i0 + 0], p[3 * i1 + 0]);
            py2[k] = pack2(p[3 * i0 + 1], p[3 * i1 + 1]);
            pz2[k] = pack2(p[3 * i0 + 2], p[3 * i1 + 2]);
        }
#pragma unroll
        for (int j = 0; j < PPT; j++) mdi[j] = 0x7f800000;   // +inf bits

        for (int i = t; i < Nn; i += 1024)
            sm->c4[i] = make_float4(p[3 * i + 0], p[3 * i + 1], p[3 * i + 2], 0.f);
        if (t == 0) sm->sel[0] = 0;
        __syncthreads();

        float4 q = sm->c4[0];

        for (int it = 1; it < NPOINT; it++) {
            ull nqx2 = pack2(-q.x, -q.x);
            ull nqy2 = pack2(-q.y, -q.y);
            ull nqz2 = pack2(-q.z, -q.z);

#pragma unroll
            for (int k = 0; k < 4; k++) {
                ull dx = add2(px2[k], nqx2);
                ull dy = add2(py2[k], nqy2);
                ull dz = add2(pz2[k], nqz2);
                ull s  = add2(add2(mul2(dx, dx), mul2(dy, dy)), mul2(dz, dz));
                float d0, d1; unpack2(s, d0, d1);
                mdi[2 * k]     = min(mdi[2 * k],     __float_as_int(d0));
                mdi[2 * k + 1] = min(mdi[2 * k + 1], __float_as_int(d1));
            }

            int m0 = max(mdi[0], mdi[1]);
            int m1 = max(mdi[2], mdi[3]);
            int m2 = max(mdi[4], mdi[5]);
            int m3 = max(mdi[6], mdi[7]);
            int m  = max(max(m0, m1), max(m2, m3));

            int wm = __reduce_max_sync(0xffffffffu, m);
            int cand = 0x7fffffff;
            if (m == wm) {
#pragma unroll
                for (int j = 0; j < PPT; j++)
                    if (mdi[j] == wm) cand = min(cand, t + j * 1024);
            }
            int widx = __reduce_min_sync(0xffffffffu, cand);
            if (lane == 0)
                sm->red[wid] = ((ull)(unsigned)wm << 32) | (unsigned)widx;
            __syncthreads();

            if (t < 32) {
                ull pk = sm->red[t];
                int v  = (int)(pk >> 32);
                int ix = (int)(unsigned)pk;
                int gm = __reduce_max_sync(0xffffffffu, v);
                int c2 = (v == gm) ? ix : 0x7fffffff;
                int win = __reduce_min_sync(0xffffffffu, c2);
                if (t == 0) { sm->sel[it] = win; sm->q = sm->c4[win]; }
            }
            __syncthreads();
            q = sm->q;
        }

        // write new_xyz (B, NPOINT, 3)
        {
            int sel = sm->sel[t];
            float4 c = sm->c4[sel];
            float* o = newxyz + ((size_t)b * NPOINT + t) * 3;
            o[0] = c.x; o[1] = c.y; o[2] = c.z;
        }
    } else {
        // =================== feat role: per-point MLP, 2 pts/thread =========
        float*  smem = (float*)raw;
        float4* sw1  = (float4*)(smem + SW1_OFF);
        float*  sw2t = smem + SW2T_OFF;
        float*  sb2  = smem + SB2_OFF;
        float*  sw3  = smem + SW3_OFF;
        float*  sb3  = smem + SB3_OFF;

        for (int o = t; o < 64; o += 1024) {
            float s1 = g1[o] / sqrtf(v1[o] + 1e-5f);
            sw1[o] = make_float4(w1[o * 3 + 0] * s1, w1[o * 3 + 1] * s1,
                                 w1[o * 3 + 2] * s1, (b1[o] - m1[o]) * s1 + be1[o]);
            float s2 = g2[o] / sqrtf(v2[o] + 1e-5f);
            sb2[o] = (b2[o] - m2[o]) * s2 + be2[o];
        }
        for (int i = t; i < 64 * 64; i += 1024) {
            int o = i >> 6, c = i & 63;
            float s2 = g2[o] / sqrtf(v2[o] + 1e-5f);
            sw2t[c * 64 + o] = w2[o * 64 + c] * s2;   // transposed [c][o]
        }
        for (int i = t; i < 128 * 64; i += 1024) {
            int o = i >> 6;
            float s3 = g3[o] / sqrtf(v3[o] + 1e-5f);
            sw3[i] = w3[i] * s3;
        }
        for (int o = t; o < 128; o += 1024) {
            float s3 = g3[o] / sqrtf(v3[o] + 1e-5f);
            sb3[o] = (b3[o] - m3[o]) * s3 + be3[o];
        }
        __syncthreads();

        const int pbase = (blockIdx.x - Bn) * FEAT_PTS;

        for (int rep = 0; rep < FEAT_PTS / 1024; rep++) {
            const int pt = pbase + rep * 1024 + t;     // global point id
            const float x = __ldg(xyz + 3 * pt + 0);
            const float y = __ldg(xyz + 3 * pt + 1);
            const float z = __ldg(xyz + 3 * pt + 2);

            ull h2p[32];
            {
                const ull* sb2p = (const ull*)sb2;
#pragma unroll
                for (int k = 0; k < 32; k++) h2p[k] = sb2p[k];
            }

            for (int c = 0; c < 64; c++) {
                float4 wc = sw1[c];
                float h1 = fmaxf(fmaf(x, wc.x, fmaf(y, wc.y, fmaf(z, wc.z, wc.w))), 0.f);
                ull h1p = pack2(h1, h1);
                const ulonglong2* row = (const ulonglong2*)(sw2t + c * 64);
#pragma unroll
                for (int k = 0; k < 16; k++) {
                    ulonglong2 w = row[k];
                    h2p[2 * k]     = fma2(w.x, h1p, h2p[2 * k]);
                    h2p[2 * k + 1] = fma2(w.y, h1p, h2p[2 * k + 1]);
                }
            }
#pragma unroll
            for (int k = 0; k < 32; k++) {
                float a, c2; unpack2(h2p[k], a, c2);
                h2p[k] = pack2(fmaxf(a, 0.f), fmaxf(c2, 0.f));
            }

            float4* outr = ft + (size_t)pt * 32;
            for (int o4 = 0; o4 < 32; o4++) {
                float vv[4];
#pragma unroll
                for (int j = 0; j < 4; j++) {
                    int o = o4 * 4 + j;
                    const ulonglong2* row = (const ulonglong2*)(sw3 + o * 64);
                    ull a0 = 0ull, a1 = 0ull;
#pragma unroll
                    for (int k = 0; k < 16; k++) {
                        ulonglong2 w = row[k];
                        a0 = fma2(w.x, h2p[2 * k],     a0);
                        a1 = fma2(w.y, h2p[2 * k + 1], a1);
                    }
                    float s0, s1, s2, s3; unpack2(a0, s0, s1); unpack2(a1, s2, s3);
                    vv[j] = fmaxf((s0 + s1) + (s2 + s3) + sb3[o], 0.f);
                }
                outr[o4] = make_float4(vv[0], vv[1], vv[2], vv[3]);
            }
        }
    }
}

// ---------------------------------------------------------------------------
// Ball query: one WARP per center; ballot + prefix-popcount ordered selection,
// per-center early exit. Exact reference arithmetic.
// ---------------------------------------------------------------------------
__global__ __launch_bounds__(256)
void bq_kernel(const float* __restrict__ xyz, const float* __restrict__ newxyz,
               int* __restrict__ ball)
{
    const int gtid = blockIdx.x * 256 + threadIdx.x;
    const int c = gtid >> 5;            // center id, 0 .. B*NPOINT-1
    const int lane = threadIdx.x & 31;
    const int b = c >> 10;
    const float* p = xyz + (size_t)b * Nn * 3;

    const float qx = __ldg(newxyz + 3 * c + 0);
    const float qy = __ldg(newxyz + 3 * c + 1);
    const float qz = __ldg(newxyz + 3 * c + 2);

    int* out = ball + (size_t)c * NSAMPLE;
    int cnt = 0;

    for (int base = 0; base < Nn; base += 32) {
        const int i = base + lane;
        float dx = __fadd_rn(__ldg(p + 3 * i + 0), -qx);
        float dy = __fadd_rn(__ldg(p + 3 * i + 1), -qy);
        float dz = __fadd_rn(__ldg(p + 3 * i + 2), -qz);
        float d  = __fadd_rn(__fadd_rn(__fmul_rn(dx, dx), __fmul_rn(dy, dy)),
                             __fmul_rn(dz, dz));
        const bool valid = d < 0.04f;
        const unsigned mask = __ballot_sync(0xffffffffu, valid);
        if (valid) {
            int pos = cnt + __popc(mask & ((1u << lane) - 1u));
            if (pos < NSAMPLE) out[pos] = i;
        }
        cnt += __popc(mask);
        if (cnt >= NSAMPLE) break;
    }
    if (cnt < NSAMPLE) {                       // reference pads with 0
        int s = cnt + lane;
        if (s < NSAMPLE) out[s] = 0;
    }
}

// ---------------------------------------------------------------------------
// Gather-max pooling: one warp per group; lane owns 4 channels (float4),
// loops over the 32 sampled points reading coalesced 512B rows (L2-resident).
// ---------------------------------------------------------------------------
__global__ __launch_bounds__(256)
void pool_kernel(const float4* __restrict__ ft, const int* __restrict__ ball,
                 float* __restrict__ feat)
{
    const int g = (blockIdx.x * 256 + threadIdx.x) >> 5;   // group id 0..8191
    const int lane = threadIdx.x & 31;
    const int b = g >> 10;
    const int s = g & 1023;

    const int myidx = __ldg(ball + (size_t)g * NSAMPLE + lane);
    const float4* base = ft + ((size_t)b * Nn) * 32;

    float4 mx = make_float4(0.f, 0.f, 0.f, 0.f);   // post-ReLU values are >= 0
#pragma unroll 4
    for (int smp = 0; smp < NSAMPLE; smp++) {
        int is = __shfl_sync(0xffffffffu, myidx, smp);
        float4 v = __ldg(base + (size_t)is * 32 + lane);
        mx.x = fmaxf(mx.x, v.x);
        mx.y = fmaxf(mx.y, v.y);
        mx.z = fmaxf(mx.z, v.z);
        mx.w = fmaxf(mx.w, v.w);
    }

    float* o = feat + ((size_t)b * 128 + lane * 4) * NPOINT + s;
    o[0 * NPOINT] = mx.x;
    o[1 * NPOINT] = mx.y;
    o[2 * NPOINT] = mx.z;
    o[3 * NPOINT] = mx.w;
}

// ---------------------------------------------------------------------------
extern "C" void kernel_launch(void* const* d_in, const int* in_sizes, int n_in,
                              void* d_out, int out_size)
{
    const float* xyz = (const float*)d_in[0];
    const float* w1  = (const float*)d_in[1];
    const float* b1  = (const float*)d_in[2];
    const float* g1  = (const float*)d_in[3];
    const float* be1 = (const float*)d_in[4];
    const float* m1  = (const float*)d_in[5];
    const float* v1  = (const float*)d_in[6];
    const float* w2  = (const float*)d_in[7];
    const float* b2  = (const float*)d_in[8];
    const float* g2  = (const float*)d_in[9];
    const float* be2 = (const float*)d_in[10];
    const float* m2  = (const float*)d_in[11];
    const float* v2  = (const float*)d_in[12];
    const float* w3  = (const float*)d_in[13];
    const float* b3  = (const float*)d_in[14];
    const float* g3  = (const float*)d_in[15];
    const float* be3 = (const float*)d_in[16];
    const float* m3  = (const float*)d_in[17];
    const float* v3  = (const float*)d_in[18];

    float* out    = (float*)d_out;
    float* newxyz = out;                             // (B, NPOINT, 3)
    float* feat   = out + (size_t)Bn * NPOINT * 3;   // (B, 128, NPOINT)

    float4* ft = nullptr;
    cudaGetSymbolAddress((void**)&ft, g_feat4);
    int* ball = nullptr;
    cudaGetSymbolAddress((void**)&ball, g_ball_idx);

    cudaFuncSetAttribute(fps_feat_kernel,
                         cudaFuncAttributeMaxDynamicSharedMemorySize, FUSED_SMEM);

    // blocks 0..7: FPS (8 SMs); blocks 8..39: per-point MLP concurrently.
    fps_feat_kernel<<<Bn + FEAT_BLOCKS, 1024, FUSED_SMEM>>>(
        xyz, newxyz,
        w1, b1, g1, be1, m1, v1,
        w2, b2, g2, be2, m2, v2,
        w3, b3, g3, be3, m3, v3,
        ft);
    bq_kernel<<<(Bn * NPOINT * 32) / 256, 256>>>(xyz, newxyz, ball);
    pool_kernel<<<(Bn * NPOINT * 32) / 256, 256>>>(ft, ball, feat);
}